// round 17
// baseline (speedup 1.0000x reference)
#include <cuda_runtime.h>
#include <cuda_fp16.h>
#include <cstdint>

// EncodecQuantizer RVQ via mma.sync fp16 two-term GEMM:
// A=[h1,h2] (fp16 split of residual) x B=[g,g] (g = fp16(e)) computes
// r.g EXACTLY; error = r.(e-g), sigma~3e-3. Tokens whose fp32 top-2 gap
// <= W=0.05 get a full fp32 rescan + fp64 recheck (exact argmax).
// MT=64 tokens/block, NT=64 codes/tile, 256 threads, 3 blocks/SM.
// x [B,T,D] f32, embed [NQ,K,D] f32 -> codes [NQ,B*T] as float32.
#define BB    16
#define TT    4096
#define DD    128
#define NQ    8
#define KK    1024
#define NTOK  (BB * TT)        // 65536
#define MT    64               // tokens per block
#define NT    64               // codes per tile
#define NTILES (KK / NT)       // 16
#define BLKT  256              // 8 warps
#define ASTR_A 528             // A row stride bytes (h1|h2: 256 fp16 + pad)
#define ASTR_B 272             // B row stride bytes (g: 128 fp16 + pad)
#define WGAP  0.05f            // rescan trigger window (~15 sigma)
#define FLTMIN (-3.402823466e+38f)

typedef unsigned long long u64;
typedef unsigned int u32;
typedef unsigned short u16;

// smem byte offsets
#define SM_A   0                                  // 64 x 528 = 33792
#define SM_B0  (SM_A + MT * ASTR_A)               // 33792
#define SM_B1  (SM_B0 + NT * ASTR_B)              // 51200
#define SM_N   (SM_B1 + NT * ASTR_B)              // 68608: 1024 f32
#define SM_MG  (SM_N + KK * 4)                    // 72704: 4 x 128 x 4B
#define SMEM_BYTES (SM_MG + 4 * 2 * MT * 4)       // 74752 (-> 3 blocks/SM)

__device__ float g_norms[NQ * KK];
__device__ __half g_e16[(size_t)NQ * KK * DD];    // g = fp16(e)

// ---------------------------------------------------------------------------
__global__ void prep_kernel(const float* __restrict__ embed) {
    int k = blockIdx.x * blockDim.x + threadIdx.x;
    if (k >= NQ * KK) return;
    const float* e = embed + (size_t)k * DD;
    __half* o = g_e16 + (size_t)k * DD;
    float s = 0.0f;
#pragma unroll 4
    for (int d = 0; d < DD; d++) {
        float v = e[d];
        s = fmaf(v, v, s);
        o[d] = __float2half_rn(v);
    }
    g_norms[k] = s;
}

// ---------------------------------------------------------------------------
__device__ __forceinline__ u32 smem_u32(const void* p) {
    u32 a;
    asm("{ .reg .u64 t; cvta.to.shared.u64 t, %1; cvt.u32.u64 %0, t; }"
        : "=r"(a) : "l"(p));
    return a;
}
__device__ __forceinline__ void ldsm_x4(u32& r0, u32& r1, u32& r2, u32& r3,
                                        u32 addr) {
    asm volatile("ldmatrix.sync.aligned.m8n8.x4.shared.b16 {%0,%1,%2,%3}, [%4];"
                 : "=r"(r0), "=r"(r1), "=r"(r2), "=r"(r3) : "r"(addr));
}
__device__ __forceinline__ void mma_f16(float* c, const u32* a,
                                        u32 b0, u32 b1) {
    asm volatile(
        "mma.sync.aligned.m16n8k16.row.col.f32.f16.f16.f32 "
        "{%0,%1,%2,%3}, {%4,%5,%6,%7}, {%8,%9}, {%0,%1,%2,%3};"
        : "+f"(c[0]), "+f"(c[1]), "+f"(c[2]), "+f"(c[3])
        : "r"(a[0]), "r"(a[1]), "r"(a[2]), "r"(a[3]), "r"(b0), "r"(b1));
}
__device__ __forceinline__ void cp16(u32 dst_smem, const void* src) {
    asm volatile("cp.async.cg.shared.global [%0], [%1], 16;"
                 :: "r"(dst_smem), "l"(src));
}
#define CP_COMMIT() asm volatile("cp.async.commit_group;" ::: "memory")
#define CP_WAIT0()  asm volatile("cp.async.wait_group 0;" ::: "memory")

#define UPD(d1, d2, q1, q2, dist, kc)                                    \
    do {                                                                 \
        if ((dist) > (d1)) { (d2) = (d1); (q2) = (q1); (d1) = (dist);    \
                             (q1) = (kc); }                              \
        else if ((dist) > (d2)) { (d2) = (dist); (q2) = (kc); }          \
    } while (0)

#define MERGE(d1, q1, d2, q2, od1, ok1, od2, ok2)                        \
    do {                                                                 \
        bool ob = ((od1) > (d1)) || ((od1) == (d1) && (ok1) < (q1));     \
        if (ob) {                                                        \
            bool sb = ((d1) > (od2)) || ((d1) == (od2) && (q1) < (ok2)); \
            (d2) = sb ? (d1) : (od2); (q2) = sb ? (q1) : (ok2);          \
            (d1) = (od1); (q1) = (ok1);                                  \
        } else {                                                         \
            bool sb = ((od1) > (d2)) || ((od1) == (d2) && (ok1) < (q2)); \
            if (sb) { (d2) = (od1); (q2) = (ok1); }                      \
        }                                                                \
    } while (0)

// ---------------------------------------------------------------------------
__global__ void __launch_bounds__(BLKT, 3)
rvq_mma_kernel(const float* __restrict__ x,
               const float* __restrict__ embed,
               float* __restrict__ codes) {
    extern __shared__ __align__(16) unsigned char smraw[];
    float* SN   = (float*)(smraw + SM_N);
    float* MGd1 = (float*)(smraw + SM_MG);            // [2][64]
    float* MGd2 = MGd1 + 2 * MT;
    int*   MGk1 = (int*)(MGd2 + 2 * MT);
    int*   MGk2 = MGk1 + 2 * MT;
    const u32 smb = smem_u32(smraw);

    const int tid  = threadIdx.x;
    const int lane = tid & 31;
    const int wid  = tid >> 5;
    const int rowgrp = wid & 3;     // 16 token-rows each
    const int nhalf  = wid >> 2;    // 0: codes 0-31 of tile, 1: codes 32-63
    const int tok0 = blockIdx.x * MT;
    const int row = tid >> 2;       // my token (0..63)
    const int q   = tid & 3;        // my quarter (32 dims)

    // ---- residual in registers: 32 floats per thread ----
    float4 rr[8];
    {
        const float4* xs = (const float4*)(x + (size_t)(tok0 + row) * DD +
                                           q * 32);
#pragma unroll
        for (int j = 0; j < 8; j++) rr[j] = xs[j];
    }

    // lane addressing for ldmatrix
    const u32 a_addr = smb + SM_A +
        (rowgrp * 16 + (lane & 15)) * ASTR_A + (((lane >> 4) << 3) * 2);
    const int b_nloc = ((lane >> 4) << 3) | (lane & 7);
    const int b_cadd = (lane & 8) ? 16 : 0;
    const u32 b_lane_off = (nhalf * 32 + b_nloc) * ASTR_B + b_cadd;
    const u32 buf_off[2] = {SM_B0, SM_B1};

    for (int s = 0; s < NQ; s++) {
        const float* es = embed + (size_t)s * KK * DD;
        const uint4* bsrc = (const uint4*)(g_e16 + (size_t)s * KK * DD);

        // ---- issue async-load of B tile 0 early (64 rows x 256B) ----
#pragma unroll
        for (int i = 0; i < 4; i++) {
            int idx = tid + i * BLKT;
            int r2 = idx >> 4, u2 = idx & 15;     // 16 uint4 per row
            cp16(smb + SM_B0 + r2 * ASTR_B + u2 * 16,
                 bsrc + (size_t)r2 * 16 + u2);
        }
        CP_COMMIT();

        // stage norms
        for (int i = tid; i < KK; i += BLKT) SN[i] = g_norms[s * KK + i];

        // ---- A rebuild: fp16 split h1 (cols 0-127) + h2 (cols 128-255) ----
        {
            unsigned char* abase = smraw + SM_A + row * ASTR_A + q * 64;
#pragma unroll
            for (int j = 0; j < 8; j++) {
                float4 v = rr[j];
                float vf[4] = {v.x, v.y, v.z, v.w};
                u16 h1[4], h2[4];
#pragma unroll
                for (int q2 = 0; q2 < 4; q2++) {
                    __half a = __float2half_rn(vf[q2]);
                    __half b = __float2half_rn(vf[q2] - __half2float(a));
                    h1[q2] = __half_as_ushort(a);
                    h2[q2] = __half_as_ushort(b);
                }
                uint2 w1 = make_uint2((u32)h1[0] | ((u32)h1[1] << 16),
                                      (u32)h1[2] | ((u32)h1[3] << 16));
                uint2 w2 = make_uint2((u32)h2[0] | ((u32)h2[1] << 16),
                                      (u32)h2[2] | ((u32)h2[3] << 16));
                *(uint2*)(abase + j * 8) = w1;          // h1 at col d
                *(uint2*)(abase + 256 + j * 8) = w2;    // h2 at col 128+d
            }
        }
        CP_WAIT0();
        __syncthreads();   // A + B0 visible

        float d1a = FLTMIN, d2a = FLTMIN, d1b = FLTMIN, d2b = FLTMIN;
        int   k1a = 0, k2a = 0, k1b = 0, k2b = 0;

        for (int t = 0; t < NTILES; t++) {
            const u32 cur = buf_off[t & 1];
            if (t + 1 < NTILES) {
                const uint4* src = bsrc + (size_t)(t + 1) * NT * 16;
                const u32 nxt = buf_off[(t + 1) & 1];
#pragma unroll
                for (int i = 0; i < 4; i++) {
                    int idx = tid + i * BLKT;
                    int r2 = idx >> 4, u2 = idx & 15;
                    cp16(smb + nxt + r2 * ASTR_B + u2 * 16,
                         src + (size_t)r2 * 16 + u2);
                }
                CP_COMMIT();
            }

            // ---- MMA: K=256 over 8 ksteps, m16 x n32 per warp.
            // Per kstep: a1 (h1), a2 (h2); b shared by both A terms.
            float acc[4][4];
#pragma unroll
            for (int i = 0; i < 4; i++) {
                acc[i][0] = 0.f; acc[i][1] = 0.f;
                acc[i][2] = 0.f; acc[i][3] = 0.f;
            }
            const u32 bbase = smb + cur + b_lane_off;
#pragma unroll
            for (int ks = 0; ks < 8; ks++) {
                u32 a1[4], a2[4];
                ldsm_x4(a1[0], a1[1], a1[2], a1[3], a_addr + ks * 32);
                ldsm_x4(a2[0], a2[1], a2[2], a2[3], a_addr + 256 + ks * 32);
                u32 b0, b1, b2, b3;
                ldsm_x4(b0, b1, b2, b3, bbase + ks * 32);           // grp0
                mma_f16(acc[0], a1, b0, b1);
                mma_f16(acc[1], a1, b2, b3);
                mma_f16(acc[0], a2, b0, b1);
                mma_f16(acc[1], a2, b2, b3);
                ldsm_x4(b0, b1, b2, b3,
                        bbase + 16 * ASTR_B + ks * 32);             // grp1
                mma_f16(acc[2], a1, b0, b1);
                mma_f16(acc[3], a1, b2, b3);
                mma_f16(acc[2], a2, b0, b1);
                mma_f16(acc[3], a2, b2, b3);
            }

            // ---- epilogue: distances + top-2 ----
#pragma unroll
            for (int nb = 0; nb < 4; nb++) {
                int kc = t * NT + nhalf * 32 + nb * 8 + (lane & 3) * 2;
                float n0 = SN[kc], n1 = SN[kc + 1];
                UPD(d1a, d2a, k1a, k2a, fmaf(2.0f, acc[nb][0], -n0), kc);
                UPD(d1a, d2a, k1a, k2a, fmaf(2.0f, acc[nb][1], -n1), kc + 1);
                UPD(d1b, d2b, k1b, k2b, fmaf(2.0f, acc[nb][2], -n0), kc);
                UPD(d1b, d2b, k1b, k2b, fmaf(2.0f, acc[nb][3], -n1), kc + 1);
            }

            if (t + 1 < NTILES) CP_WAIT0();
            __syncthreads();
        }

        // ---- merge across the 4 lanes of each quad ----
#pragma unroll
        for (int m = 1; m < 4; m <<= 1) {
            float od1 = __shfl_xor_sync(0xffffffffu, d1a, m);
            int   ok1 = __shfl_xor_sync(0xffffffffu, k1a, m);
            float od2 = __shfl_xor_sync(0xffffffffu, d2a, m);
            int   ok2 = __shfl_xor_sync(0xffffffffu, k2a, m);
            MERGE(d1a, k1a, d2a, k2a, od1, ok1, od2, ok2);
            od1 = __shfl_xor_sync(0xffffffffu, d1b, m);
            ok1 = __shfl_xor_sync(0xffffffffu, k1b, m);
            od2 = __shfl_xor_sync(0xffffffffu, d2b, m);
            ok2 = __shfl_xor_sync(0xffffffffu, k2b, m);
            MERGE(d1b, k1b, d2b, k2b, od1, ok1, od2, ok2);
        }

        // ---- quad leaders publish per-(token, nhalf) top-2 ----
        if ((lane & 3) == 0) {
            int tA = rowgrp * 16 + (lane >> 2);
            int iA = nhalf * MT + tA;
            MGd1[iA] = d1a; MGd2[iA] = d2a; MGk1[iA] = k1a; MGk2[iA] = k2a;
            int iB = iA + 8;
            MGd1[iB] = d1b; MGd2[iB] = d2b; MGk1[iB] = k1b; MGk2[iB] = k2b;
        }
        __syncthreads();

        // ---- final merge; rescan + fp64 recheck when gap <= W ----
        int kbest;
        {
            float f1 = MGd1[row], f2v = MGd2[row];
            int   c1 = MGk1[row], c2 = MGk2[row];
            float o1 = MGd1[MT + row], o2 = MGd2[MT + row];
            int   oc1 = MGk1[MT + row], oc2 = MGk2[MT + row];
            MERGE(f1, c1, f2v, c2, o1, oc1, o2, oc2);
            kbest = c1;
            if (f1 - f2v <= WGAP) {
                // Full fp32 rescan (quad-cooperative, dims split by q).
                // Exact register residual vs fp32 codebook: same accuracy
                // tier as the proven fp32 kernels (~1e-3 dot noise).
                float t1 = FLTMIN, t2 = FLTMIN;
                int   n1i = 0, n2i = 0;
                unsigned mk = __activemask();
                for (int k = 0; k < KK; k++) {
                    const float4* ep =
                        (const float4*)(es + (size_t)k * DD + q * 32);
                    float dp = 0.0f;
#pragma unroll
                    for (int j = 0; j < 8; j++) {
                        float4 ev = __ldg(ep + j);
                        dp = fmaf(rr[j].x, ev.x, dp);
                        dp = fmaf(rr[j].y, ev.y, dp);
                        dp = fmaf(rr[j].z, ev.z, dp);
                        dp = fmaf(rr[j].w, ev.w, dp);
                    }
                    dp += __shfl_xor_sync(mk, dp, 1);
                    dp += __shfl_xor_sync(mk, dp, 2);
                    float dist = fmaf(2.0f, dp, -SN[k]);
                    UPD(t1, t2, n1i, n2i, dist, k);
                }
                // fp64 recheck of the rescan top-2 (exact argmax decision)
                const float* e1p = es + (size_t)n1i * DD + q * 32;
                const float* e2p = es + (size_t)n2i * DD + q * 32;
                double q1 = 0.0, q2 = 0.0;
#pragma unroll
                for (int j = 0; j < 8; j++) {
                    float4 v = rr[j];
                    float vf[4] = {v.x, v.y, v.z, v.w};
#pragma unroll
                    for (int c = 0; c < 4; c++) {
                        double rv = (double)vf[c];
                        double a = (double)__ldg(e1p + j * 4 + c);
                        double b = (double)__ldg(e2p + j * 4 + c);
                        q1 += rv * a - 0.5 * a * a;
                        q2 += rv * b - 0.5 * b * b;
                    }
                }
                q1 += __shfl_xor_sync(mk, q1, 1);
                q1 += __shfl_xor_sync(mk, q1, 2);
                q2 += __shfl_xor_sync(mk, q2, 1);
                q2 += __shfl_xor_sync(mk, q2, 2);
                kbest = (q2 > q1 || (q2 == q1 && n2i < n1i)) ? n2i : n1i;
            }
            if (q == 0)
                codes[(size_t)s * NTOK + tok0 + row] = (float)kbest;
        }

        // ---- residual update in registers (fp32 exact) ----
        {
            const float4* eb =
                (const float4*)(es + (size_t)kbest * DD + q * 32);
#pragma unroll
            for (int j = 0; j < 8; j++) {
                float4 ev = eb[j];
                rr[j].x -= ev.x; rr[j].y -= ev.y;
                rr[j].z -= ev.z; rr[j].w -= ev.w;
            }
        }
        __syncthreads();   // MG reads done before next stage overwrites
    }
}

// ---------------------------------------------------------------------------
extern "C" void kernel_launch(void* const* d_in, const int* in_sizes, int n_in,
                              void* d_out, int out_size) {
    const float* p0 = (const float*)d_in[0];
    const float* p1 = (const float*)d_in[1];
    const float* x;
    const float* embed;
    if (in_sizes[0] > in_sizes[1]) { x = p0; embed = p1; }
    else                           { x = p1; embed = p0; }
    float* codes = (float*)d_out;

    cudaFuncSetAttribute(rvq_mma_kernel,
                         cudaFuncAttributeMaxDynamicSharedMemorySize,
                         SMEM_BYTES);

    prep_kernel<<<(NQ * KK + 127) / 128, 128>>>(embed);
    rvq_mma_kernel<<<NTOK / MT, BLKT, SMEM_BYTES>>>(x, embed, codes);
}